// round 2
// baseline (speedup 1.0000x reference)
#include <cuda_runtime.h>
#include <math.h>

#define T_LEN    8192
#define NDELAY   360
#define NTHREADS 512
#define MAXK     4

// ---------------------------------------------------------------------------
// Single fused kernel. One CTA per batch row.
//
// Math: straight-through Gumbel one-hot is exactly hard in fp32 for the zero
// entries, so the 420-tap filter has exactly two taps:
//     y_t = x_t - a1*y_{t-L1} - a2*y_{t-L2},   L1,L2 >= 61
// i.e. y = x / (1+s),  s = a1 z^-L1 + a2 z^-L2.
// Squaring trick:  y = x(1-s)(1+s^2)...(1+s^{2^{K-1}}) / (1 - s^{2^K})
//   phase 1 (parallel FIR stages): w = (1-s)(1+s^2)...x
//   phase 2 (serial chunks of width 2^K*min(L1,L2)): y_t = w_t + [s^{2^K} y]_t
// ---------------------------------------------------------------------------
__global__ void __launch_bounds__(NTHREADS)
ks_fused_kernel(const float* __restrict__ x,
                const float* __restrict__ gumbel,
                const float* __restrict__ delayp,
                const float* __restrict__ fb,
                const float* __restrict__ rc,
                float* __restrict__ out) {
    extern __shared__ float smem[];
    float* bufA = smem;            // 8192 floats
    float* bufB = smem + T_LEN;    // 8192 floats

    __shared__ float s_rv[16];
    __shared__ int   s_ri[16];
    __shared__ int   s_m;
    __shared__ float s_coef[24];
    __shared__ int   s_lag[24];

    const int tid  = threadIdx.x;
    const int row  = blockIdx.x;
    const int lane = tid & 31;
    const int wid  = tid >> 5;

    // --- 1. issue staging loads early (hide DRAM latency under setup) ---
    const float4* x4 = (const float4*)(x + (size_t)row * T_LEN);
    float4 stg[4];
#pragma unroll
    for (int i = 0; i < 4; i++) stg[i] = x4[tid + i * NTHREADS];

    // --- 2. argmax over 360 logits (first-index tie-break) ---
    float lv = -INFINITY;
    int   li = tid;
    if (tid < NDELAY) lv = delayp[tid] + gumbel[tid];
#pragma unroll
    for (int off = 16; off > 0; off >>= 1) {
        float ov = __shfl_down_sync(0xffffffffu, lv, off);
        int   oi = __shfl_down_sync(0xffffffffu, li, off);
        if (ov > lv || (ov == lv && oi < li)) { lv = ov; li = oi; }
    }
    if (lane == 0) { s_rv[wid] = lv; s_ri[wid] = li; }
    __syncthreads();
    if (wid == 0) {
        lv = (lane < 16) ? s_rv[lane] : -INFINITY;
        li = (lane < 16) ? s_ri[lane] : 0x7fffffff;
#pragma unroll
        for (int off = 8; off > 0; off >>= 1) {
            float ov = __shfl_down_sync(0xffffffffu, lv, off);
            int   oi = __shfl_down_sync(0xffffffffu, li, off);
            if (ov > lv || (ov == lv && oi < li)) { lv = ov; li = oi; }
        }
        if (lane == 0) s_m = li;
    }
    __syncthreads();

    // --- 3. every thread computes scalar coefficients (redundant, cheap) ---
    const int m = s_m;
    float k1 = tanhf(tanhf(rc[0]));
    float k2 = tanhf(tanhf(rc[1]));
    float a1 = k1 * (1.0f - k2);
    float a2 = fminf(fmaxf(k2, -0.999f), 0.999f);
    float bound = 0.999f - fabsf(a2);
    a1 = fminf(fmaxf(a1, -bound), bound);
    float g = powf(1.0f / (1.0f + expf(-fb[0])), 0.45f);
    a1 *= g;
    a2 *= g;
    const int L1 = 61 + m;
    const int L2 = 61 + ((m + 1) % NDELAY);
    const int C  = (L1 < L2) ? L1 : L2;

    // --- 4. pick expansion level K by cost model (cycles) ---
    int K = 1;
    {
        const float stage_cost[MAXK] = {1024.f, 1280.f, 1792.f, 2816.f};
        float p1 = 0.f, best = 1e30f;
        for (int k = 1; k <= MAXK; k++) {
            p1 += stage_cost[k - 1];
            int W  = C << k;
            int ch = (T_LEN + W - 1) / W;
            float cost = p1 + 90.f * (float)ch;
            if (cost < best) { best = cost; K = k; }
        }
    }

    // --- 5. commit staged x to SMEM ---
    {
        float4* a4 = (float4*)bufA;
#pragma unroll
        for (int i = 0; i < 4; i++) a4[tid + i * NTHREADS] = stg[i];
    }
    __syncthreads();

    // --- 6. phase 1: staged FIR,  w <- (1-s)(1+s^2)...(1+s^{2^{K-1}}) x ---
    float* cur = bufA;
    float* nxt = bufB;
    for (int k = 1; k <= K; k++) {
        const int n = 1 << (k - 1);   // this stage applies (1 +/- s^n)
        if (tid == 0) {
            const float sign = (k == 1) ? -1.0f : 1.0f;
            for (int i = 0; i <= n; i++) {
                float bb = 1.0f;                       // C(n,i)
                for (int q = 0; q < i; q++) bb = bb * (float)(n - q) / (float)(q + 1);
                float t = bb;
                for (int q = 0; q < i; q++)     t *= a1;
                for (int q = 0; q < n - i; q++) t *= a2;
                s_coef[i] = sign * t;
                s_lag[i]  = i * L1 + (n - i) * L2;
            }
        }
        __syncthreads();
        const int nt = n + 1;
#pragma unroll
        for (int i = 0; i < T_LEN / NTHREADS; i++) {
            const int t = i * NTHREADS + tid;
            float acc = cur[t];
            for (int j = 0; j < nt; j++) {
                const int lg = s_lag[j];
                if (t >= lg) acc += s_coef[j] * cur[t - lg];
            }
            nxt[t] = acc;
        }
        __syncthreads();
        float* tmp = cur; cur = nxt; nxt = tmp;
    }

    // --- 7. terms for phase 2:  y_t = w_t + [s^{2^K} y]_t  (sign +) ---
    {
        const int n = 1 << K;
        if (tid == 0) {
            for (int i = 0; i <= n; i++) {
                float bb = 1.0f;
                for (int q = 0; q < i; q++) bb = bb * (float)(n - q) / (float)(q + 1);
                float t = bb;
                for (int q = 0; q < i; q++)     t *= a1;
                for (int q = 0; q < n - i; q++) t *= a2;
                s_coef[i] = t;
                s_lag[i]  = i * L1 + (n - i) * L2;
            }
        }
        __syncthreads();
    }

    // --- 8. phase 2: serial chunks of width W = C<<K, in place over w ---
    {
        const int n  = 1 << K;
        const int nt = n + 1;
        const int W  = C << K;   // == min lag of s^{2^K}
        for (int s0 = 0; s0 < T_LEN; s0 += W) {
            const int end = (s0 + W < T_LEN) ? s0 + W : T_LEN;
            for (int t = s0 + tid; t < end; t += NTHREADS) {
                float acc = cur[t];
                for (int j = 0; j < nt; j++) {
                    const int lg = s_lag[j];
                    if (t >= lg) acc += s_coef[j] * cur[t - lg];
                }
                cur[t] = acc;
            }
            __syncthreads();
        }
    }

    // --- 9. coalesced writeback ---
    {
        float4* o4 = (float4*)(out + (size_t)row * T_LEN);
        const float4* c4 = (const float4*)cur;
#pragma unroll
        for (int i = 0; i < 4; i++) o4[tid + i * NTHREADS] = c4[tid + i * NTHREADS];
    }
}

// ---------------------------------------------------------------------------
// inputs: excitation[128*8192] f32, gumbel[360], delay_param[360],
//         feedback_gain[1], reflection_coeffs[2]; output f32 [128*8192]
// ---------------------------------------------------------------------------
extern "C" void kernel_launch(void* const* d_in, const int* in_sizes, int n_in,
                              void* d_out, int out_size) {
    const float* x      = (const float*)d_in[0];
    const float* gumbel = (const float*)d_in[1];
    const float* delayp = (const float*)d_in[2];
    const float* fb     = (const float*)d_in[3];
    const float* rc     = (const float*)d_in[4];
    float* out = (float*)d_out;

    const int rows = in_sizes[0] / T_LEN;
    const int smem_bytes = 2 * T_LEN * sizeof(float);

    cudaFuncSetAttribute(ks_fused_kernel,
                         cudaFuncAttributeMaxDynamicSharedMemorySize, smem_bytes);
    ks_fused_kernel<<<rows, NTHREADS, smem_bytes>>>(x, gumbel, delayp, fb, rc, out);
}

// round 3
// speedup vs baseline: 1.5581x; 1.5581x over previous
#include <cuda_runtime.h>
#include <math.h>

#define T_LEN    8192
#define NDELAY   360
#define NTHREADS 512
#define ELEMS    (T_LEN / NTHREADS)   // 16

// ---------------------------------------------------------------------------
// Single fused kernel, one CTA per batch row.
//
// Two-tap IIR (straight-through one-hot is exactly hard in fp32):
//     y = x / (1 + s),   s = a1 z^-L1 + a2 z^-L2,  L1,L2 in [61,420]
// Fixed K=2 squaring:  y = x (1-s)(1+s^2) / (1 - s^4)
//   stage1 FIR: (1-s)      -> 2 taps          (parallel)
//   stage2 FIR: (1+s^2)    -> 3 taps          (parallel)
//   phase2 IIR: y_t = w_t + [s^4 y]_t, 5 taps, min lag 4*min(L1,L2)
//               -> serial chunks of width 4C  (4x fewer barriers than R1)
// All tap coefficients/lags are uniform registers; bodies fully unrolled.
// ---------------------------------------------------------------------------
__global__ void __launch_bounds__(NTHREADS)
ks_fused_kernel(const float* __restrict__ x,
                const float* __restrict__ gumbel,
                const float* __restrict__ delayp,
                const float* __restrict__ fb,
                const float* __restrict__ rc,
                float* __restrict__ out) {
    extern __shared__ float smem[];
    float* bufA = smem;            // 8192 floats
    float* bufB = smem + T_LEN;    // 8192 floats

    __shared__ float s_rv[16];
    __shared__ int   s_ri[16];
    __shared__ int   s_m;

    const int tid  = threadIdx.x;
    const int row  = blockIdx.x;
    const int lane = tid & 31;
    const int wid  = tid >> 5;

    // --- 1. issue staging loads early (hide DRAM latency under setup) ---
    const float4* x4 = (const float4*)(x + (size_t)row * T_LEN);
    float4 stg[4];
#pragma unroll
    for (int i = 0; i < 4; i++) stg[i] = x4[tid + i * NTHREADS];

    // --- 2. argmax over 360 logits (first-index tie-break) ---
    float lv = -INFINITY;
    int   li = tid;
    if (tid < NDELAY) lv = delayp[tid] + gumbel[tid];
#pragma unroll
    for (int off = 16; off > 0; off >>= 1) {
        float ov = __shfl_down_sync(0xffffffffu, lv, off);
        int   oi = __shfl_down_sync(0xffffffffu, li, off);
        if (ov > lv || (ov == lv && oi < li)) { lv = ov; li = oi; }
    }
    if (lane == 0) { s_rv[wid] = lv; s_ri[wid] = li; }
    __syncthreads();
    if (wid == 0) {
        lv = (lane < 16) ? s_rv[lane] : -INFINITY;
        li = (lane < 16) ? s_ri[lane] : 0x7fffffff;
#pragma unroll
        for (int off = 8; off > 0; off >>= 1) {
            float ov = __shfl_down_sync(0xffffffffu, lv, off);
            int   oi = __shfl_down_sync(0xffffffffu, li, off);
            if (ov > lv || (ov == lv && oi < li)) { lv = ov; li = oi; }
        }
        if (lane == 0) s_m = li;
    }

    // --- 3. scalar coefficients (computed redundantly per thread) ---
    float k1 = tanhf(tanhf(rc[0]));
    float k2 = tanhf(tanhf(rc[1]));
    float a1 = k1 * (1.0f - k2);
    float a2 = fminf(fmaxf(k2, -0.999f), 0.999f);
    float bound = 0.999f - fabsf(a2);
    a1 = fminf(fmaxf(a1, -bound), bound);
    float g = powf(1.0f / (1.0f + expf(-fb[0])), 0.45f);
    a1 *= g;
    a2 *= g;

    // --- 4. commit staged x to SMEM, then read argmax result ---
    {
        float4* a4 = (float4*)bufA;
#pragma unroll
        for (int i = 0; i < 4; i++) a4[tid + i * NTHREADS] = stg[i];
    }
    __syncthreads();

    const int m  = s_m;
    const int L1 = 61 + m;
    const int L2 = 61 + ((m + 1) % NDELAY);
    const int C  = (L1 < L2) ? L1 : L2;

    // --- 5. stage 1: bufB = (1 - s) * bufA   (2 taps, all in registers) ---
#pragma unroll
    for (int i = 0; i < ELEMS; i++) {
        const int t = i * NTHREADS + tid;
        float acc = bufA[t];
        if (t >= L1) acc -= a1 * bufA[t - L1];
        if (t >= L2) acc -= a2 * bufA[t - L2];
        bufB[t] = acc;
    }
    __syncthreads();

    // --- 6. stage 2: bufA = (1 + s^2) * bufB   (3 taps) ---
    {
        const float c20 = a2 * a2;
        const float c21 = 2.0f * a1 * a2;
        const float c22 = a1 * a1;
        const int   g20 = 2 * L2;
        const int   g21 = L1 + L2;
        const int   g22 = 2 * L1;
#pragma unroll
        for (int i = 0; i < ELEMS; i++) {
            const int t = i * NTHREADS + tid;
            float acc = bufB[t];
            if (t >= g20) acc += c20 * bufB[t - g20];
            if (t >= g21) acc += c21 * bufB[t - g21];
            if (t >= g22) acc += c22 * bufB[t - g22];
            bufA[t] = acc;
        }
    }
    __syncthreads();

    // --- 7. phase 2: y_t = w_t + [s^4 y]_t, in place on bufA ---
    {
        const float a1_2 = a1 * a1, a2_2 = a2 * a2;
        const float c0 = a2_2 * a2_2;            // a2^4
        const float c1 = 4.0f * a1 * a2 * a2_2;  // 4 a1 a2^3
        const float c2 = 6.0f * a1_2 * a2_2;     // 6 a1^2 a2^2
        const float c3 = 4.0f * a1 * a1_2 * a2;  // 4 a1^3 a2
        const float c4 = a1_2 * a1_2;            // a1^4
        const int   g0 = 4 * L2;
        const int   g1 = L1 + 3 * L2;
        const int   g2 = 2 * L1 + 2 * L2;
        const int   g3 = 3 * L1 + L2;
        const int   g4 = 4 * L1;
        const int   W  = 4 * C;   // min lag of s^4 -> chunk width

        for (int s0 = 0; s0 < T_LEN; s0 += W) {
            const int end = (s0 + W < T_LEN) ? (s0 + W) : T_LEN;
            for (int t = s0 + tid; t < end; t += NTHREADS) {
                float acc = bufA[t];
                float v0 = (t >= g0) ? bufA[t - g0] : 0.0f;
                float v1 = (t >= g1) ? bufA[t - g1] : 0.0f;
                float v2 = (t >= g2) ? bufA[t - g2] : 0.0f;
                float v3 = (t >= g3) ? bufA[t - g3] : 0.0f;
                float v4 = (t >= g4) ? bufA[t - g4] : 0.0f;
                acc += c0 * v0;
                acc += c1 * v1;
                acc += c2 * v2;
                acc += c3 * v3;
                acc += c4 * v4;
                bufA[t] = acc;
            }
            __syncthreads();
        }
    }

    // --- 8. coalesced writeback ---
    {
        float4* o4 = (float4*)(out + (size_t)row * T_LEN);
        const float4* c4p = (const float4*)bufA;
#pragma unroll
        for (int i = 0; i < 4; i++) o4[tid + i * NTHREADS] = c4p[tid + i * NTHREADS];
    }
}

// ---------------------------------------------------------------------------
// inputs: excitation[128*8192] f32, gumbel[360], delay_param[360],
//         feedback_gain[1], reflection_coeffs[2]; output f32 [128*8192]
// ---------------------------------------------------------------------------
extern "C" void kernel_launch(void* const* d_in, const int* in_sizes, int n_in,
                              void* d_out, int out_size) {
    const float* x      = (const float*)d_in[0];
    const float* gumbel = (const float*)d_in[1];
    const float* delayp = (const float*)d_in[2];
    const float* fb     = (const float*)d_in[3];
    const float* rc     = (const float*)d_in[4];
    float* out = (float*)d_out;

    const int rows = in_sizes[0] / T_LEN;
    const int smem_bytes = 2 * T_LEN * sizeof(float);

    cudaFuncSetAttribute(ks_fused_kernel,
                         cudaFuncAttributeMaxDynamicSharedMemorySize, smem_bytes);
    ks_fused_kernel<<<rows, NTHREADS, smem_bytes>>>(x, gumbel, delayp, fb, rc, out);
}

// round 4
// speedup vs baseline: 1.5952x; 1.0238x over previous
#include <cuda_runtime.h>
#include <math.h>

#define T_LEN    8192
#define NDELAY   360
#define NTHREADS 1024
#define ELEMS    (T_LEN / NTHREADS)      // 8
#define PAD      3392                    // >= 8*L1max = 3352, multiple of 4
#define BUF_LEN  (T_LEN + PAD)

// ---------------------------------------------------------------------------
// Two-tap IIR (straight-through one-hot is exactly hard in fp32):
//   y = x / (1+s),  s = a1 z^-L1 + a2 z^-L2,  61 <= L1,L2 <= 420
// Denominator squaring:
//   1/(1+s) = (1-s)(1+s^2).../(1 - s^{2^K})
// Phase 1: K parallel FIR passes. Phase 2: serial chunks of width 2^K * C,
// C = min(L1,L2). K=3 when C small, else K=2. Buffers are zero-padded in
// front so no tap needs a bounds guard (bare LDS+FFMA).
// ---------------------------------------------------------------------------

template <int NTAPS>
__device__ __forceinline__ void fir_pass(const float* __restrict__ src,
                                         float* __restrict__ dst,
                                         const float* coef, const int* lag,
                                         int tid) {
#pragma unroll
    for (int i = 0; i < ELEMS; i++) {
        const int t = i * NTHREADS + tid;
        float v[NTAPS];
#pragma unroll
        for (int j = 0; j < NTAPS; j++) v[j] = src[t - lag[j]];
        float acc = src[t];
#pragma unroll
        for (int j = 0; j < NTAPS; j++) acc += coef[j] * v[j];
        dst[t] = acc;
    }
    __syncthreads();
}

template <int NTAPS>
__device__ __forceinline__ void iir_chunks(float* __restrict__ buf,
                                           const float* coef, const int* lag,
                                           int W, int tid) {
    for (int s0 = 0; s0 < T_LEN; s0 += W) {
        const int end = (s0 + W < T_LEN) ? (s0 + W) : T_LEN;
        for (int t = s0 + tid; t < end; t += NTHREADS) {
            float v[NTAPS];
#pragma unroll
            for (int j = 0; j < NTAPS; j++) v[j] = buf[t - lag[j]];
            float acc = buf[t];
#pragma unroll
            for (int j = 0; j < NTAPS; j++) acc += coef[j] * v[j];
            buf[t] = acc;
        }
        __syncthreads();
    }
}

__global__ void __launch_bounds__(NTHREADS)
ks_fused_kernel(const float* __restrict__ x,
                const float* __restrict__ gumbel,
                const float* __restrict__ delayp,
                const float* __restrict__ fb,
                const float* __restrict__ rc,
                float* __restrict__ out) {
    extern __shared__ float smem[];
    float* bufA = smem;                 // [BUF_LEN]; data at +PAD
    float* bufB = smem + BUF_LEN;       // [BUF_LEN]; data at +PAD
    float* A = bufA + PAD;              // data pointers
    float* B = bufB + PAD;

    __shared__ float s_rv[32];
    __shared__ int   s_ri[32];
    __shared__ int   s_m;

    const int tid  = threadIdx.x;
    const int row  = blockIdx.x;
    const int lane = tid & 31;
    const int wid  = tid >> 5;

    // --- 1. issue staging loads early (hide DRAM latency under setup) ---
    const float4* x4 = (const float4*)(x + (size_t)row * T_LEN);
    float4 stg[ELEMS / 4];
#pragma unroll
    for (int i = 0; i < ELEMS / 4; i++) stg[i] = x4[tid + i * NTHREADS];

    // --- 2. zero both pads ---
#pragma unroll
    for (int i = 0; i < (PAD + NTHREADS - 1) / NTHREADS; i++) {
        const int p = i * NTHREADS + tid;
        if (p < PAD) { bufA[p] = 0.0f; bufB[p] = 0.0f; }
    }

    // --- 3. argmax over 360 logits (first-index tie-break) ---
    float lv = -INFINITY;
    int   li = tid;
    if (tid < NDELAY) lv = delayp[tid] + gumbel[tid];
#pragma unroll
    for (int off = 16; off > 0; off >>= 1) {
        float ov = __shfl_down_sync(0xffffffffu, lv, off);
        int   oi = __shfl_down_sync(0xffffffffu, li, off);
        if (ov > lv || (ov == lv && oi < li)) { lv = ov; li = oi; }
    }
    if (lane == 0) { s_rv[wid] = lv; s_ri[wid] = li; }
    __syncthreads();
    if (wid == 0) {
        lv = s_rv[lane];
        li = s_ri[lane];
#pragma unroll
        for (int off = 16; off > 0; off >>= 1) {
            float ov = __shfl_down_sync(0xffffffffu, lv, off);
            int   oi = __shfl_down_sync(0xffffffffu, li, off);
            if (ov > lv || (ov == lv && oi < li)) { lv = ov; li = oi; }
        }
        if (lane == 0) s_m = li;
    }

    // --- 4. scalar coefficients (redundant per thread, cheap) ---
    float k1 = tanhf(tanhf(rc[0]));
    float k2 = tanhf(tanhf(rc[1]));
    float a1 = k1 * (1.0f - k2);
    float a2 = fminf(fmaxf(k2, -0.999f), 0.999f);
    float bound = 0.999f - fabsf(a2);
    a1 = fminf(fmaxf(a1, -bound), bound);
    float g = powf(1.0f / (1.0f + expf(-fb[0])), 0.45f);
    a1 *= g;
    a2 *= g;

    // --- 5. commit staged x to SMEM (data region of bufA) ---
    {
        float4* a4 = (float4*)A;
#pragma unroll
        for (int i = 0; i < ELEMS / 4; i++) a4[tid + i * NTHREADS] = stg[i];
    }
    __syncthreads();

    const int m  = s_m;
    const int L1 = 61 + m;
    const int L2 = 61 + ((m + 1) % NDELAY);
    const int C  = (L1 < L2) ? L1 : L2;

    // powers of a1/a2
    const float a1_2 = a1 * a1, a2_2 = a2 * a2;
    const float a1_3 = a1_2 * a1, a2_3 = a2_2 * a2;
    const float a1_4 = a1_2 * a1_2, a2_4 = a2_2 * a2_2;

    // --- 6. pass A: B = (1 - s) A ---
    {
        const float c[2] = { -a1, -a2 };
        const int   l[2] = { L1, L2 };
        fir_pass<2>(A, B, c, l, tid);
    }
    // --- 7. pass B: A = (1 + s^2) B ---
    {
        const float c[3] = { a1_2, 2.0f * a1 * a2, a2_2 };
        const int   l[3] = { 2 * L1, L1 + L2, 2 * L2 };
        fir_pass<3>(B, A, c, l, tid);
    }

    const float s4c[5] = { a1_4, 4.0f * a1_3 * a2, 6.0f * a1_2 * a2_2,
                           4.0f * a1 * a2_3, a2_4 };
    const int   s4l[5] = { 4 * L1, 3 * L1 + L2, 2 * L1 + 2 * L2,
                           L1 + 3 * L2, 4 * L2 };

    float* res;
    if (C <= 150) {
        // --- K=3: pass C: B = (1 + s^4) A; then y += s^8 y, width 8C ---
        fir_pass<5>(A, B, s4c, s4l, tid);
        const float c[9] = { a1_4 * a1_4, 8.0f * a1_4 * a1_3 * a2,
                             28.0f * a1_4 * a1_2 * a2_2, 56.0f * a1_4 * a1 * a2_3,
                             70.0f * a1_4 * a2_4, 56.0f * a1_3 * a2_4 * a2,
                             28.0f * a1_2 * a2_4 * a2_2, 8.0f * a1 * a2_4 * a2_3,
                             a2_4 * a2_4 };
        const int   l[9] = { 8 * L1, 7 * L1 + L2, 6 * L1 + 2 * L2,
                             5 * L1 + 3 * L2, 4 * L1 + 4 * L2, 3 * L1 + 5 * L2,
                             2 * L1 + 6 * L2, L1 + 7 * L2, 8 * L2 };
        iir_chunks<9>(B, c, l, 8 * C, tid);
        res = B;
    } else {
        // --- K=2: y += s^4 y on A, width 4C ---
        iir_chunks<5>(A, s4c, s4l, 4 * C, tid);
        res = A;
    }

    // --- 8. coalesced writeback ---
    {
        float4* o4 = (float4*)(out + (size_t)row * T_LEN);
        const float4* r4 = (const float4*)res;
#pragma unroll
        for (int i = 0; i < ELEMS / 4; i++) o4[tid + i * NTHREADS] = r4[tid + i * NTHREADS];
    }
}

// ---------------------------------------------------------------------------
// inputs: excitation[128*8192] f32, gumbel[360], delay_param[360],
//         feedback_gain[1], reflection_coeffs[2]; output f32 [128*8192]
// ---------------------------------------------------------------------------
extern "C" void kernel_launch(void* const* d_in, const int* in_sizes, int n_in,
                              void* d_out, int out_size) {
    const float* x      = (const float*)d_in[0];
    const float* gumbel = (const float*)d_in[1];
    const float* delayp = (const float*)d_in[2];
    const float* fb     = (const float*)d_in[3];
    const float* rc     = (const float*)d_in[4];
    float* out = (float*)d_out;

    const int rows = in_sizes[0] / T_LEN;
    const int smem_bytes = 2 * BUF_LEN * sizeof(float);

    cudaFuncSetAttribute(ks_fused_kernel,
                         cudaFuncAttributeMaxDynamicSharedMemorySize, smem_bytes);
    ks_fused_kernel<<<rows, NTHREADS, smem_bytes>>>(x, gumbel, delayp, fb, rc, out);
}